// round 10
// baseline (speedup 1.0000x reference)
#include <cuda_runtime.h>
#include <math.h>

#define BATCH      262144
#define N_LEAVES   64
#define N_INTERNAL 63

#define CHILD_EPS  2.2204460492503131e-16
#define BYPASS_TH  0.9999999999999998   /* 1 - DBL_EPSILON */
#define CLAMP_V    1e300
#define PI_D       3.141592653589793
#define LN2_D      0.6931471805599453

// Folded parameters (built by prep kernel).
static __device__ double g_g  [N_INTERNAL * 8];  // folded gates (double, for fold step)
static __device__ float4 g_gf4[126];             // per side: (p0,p1,p2,0) as float
static __device__ double g_gp3[126];             // per side: p3 (double)
static __device__ float4 g_r0f[N_LEAVES];        // round-0 folded coeffs per leaf (c0,c1,c2,0)

// 2/pi fraction bits (fdlibm two_over_pi), prepended zero word.
static __device__ const unsigned long long PH_TAB[21] = {
    0x0000000000000000ULL,
    0xA2F9836E4E441529ULL, 0xFC2757D1F534DDC0ULL, 0xDB6295993C439041ULL,
    0xFE5163ABDEBBC561ULL, 0xB7246E3A424DD2E0ULL, 0x06492EEA09D1921CULL,
    0xFE1DEB1CB129A73EULL, 0xE88235F52EBB4484ULL, 0xE99C7026B45F7E41ULL,
    0x3991D639835339F4ULL, 0x9C845F8BBDF9283BULL, 0x1FF897FFDE05980FULL,
    0xEF2F118B5A0A6D1FULL, 0x6D367ECF27CB09B7ULL, 0x4F463F669E5FEA2DULL,
    0x7527BAC7EBE5F17BULL, 0x3D0739F78A5292EAULL, 0x6BFB5FB11F8D5D08ULL,
    0x56033046FC7B6BABULL, 0xF0CFBC209AF4361DULL
};

__device__ __forceinline__ double clampd(double v) {
    double r = fmin(fmax(v, -CLAMP_V), CLAMP_V);
    return (v != v) ? 0.0 : r;     // inf*0 corner -> 0 like reference nan_to_num
}

// Branchless double-range exp with fp32 core. Overflows to +inf for a>~709.78
// (reference exp does too; clamp downstream handles it).
__device__ __forceinline__ double fast_exp(double a) {
    double ac = fmin(fmax(a, -746.0), 710.0);
    double kd = rint(ac * 1.4426950408889634);
    double r  = fma(-kd, 0.6931471805599453, ac);
    r         = fma(-kd, 2.3190468138462996e-17, r);
    int k  = (int)kd;
    int k1 = k >> 1, k2 = k - k1;
    double s1 = __longlong_as_double((long long)(k1 + 1023) << 52);
    double s2 = __longlong_as_double((long long)(k2 + 1023) << 52);
    return ((double)__expf((float)r) * s1) * s2;
}

// complex log, fp32 core after 2^k scaling.
__device__ __forceinline__ void fast_clog(double x, double y, double& lr_, double& li_) {
    long long bx = __double_as_longlong(x) & 0x7fffffffffffffffLL;
    long long by = __double_as_longlong(y) & 0x7fffffffffffffffLL;
    int ex = (int)(bx >> 52), ey = (int)(by >> 52);
    int em = ex > ey ? ex : ey;
    int k  = 1022 - em;
    double s = (k >= -1022)
        ? __longlong_as_double((long long)(k + 1023) << 52)
        : __longlong_as_double((long long)(23) << 52)                 // 2^-1000
          * __longlong_as_double((long long)(k + 1000 + 1023) << 52);
    float xsf = (float)(x * s), ysf = (float)(y * s);
    float m2  = fmaf(xsf, xsf, ysf * ysf);
    lr_ = (0.5 * (double)__log2f(m2) + (double)(em - 1022)) * LN2_D;
    li_ = (double)atan2f(ysf, xsf);
}

// Branchless sincos for any finite double: compute double Cody-Waite AND
// Payne-Hanek reduction, select the angle, single __sincosf.
__device__ __forceinline__ void fast_sincos(const unsigned long long* __restrict__ ph,
                                            double a, double& s, double& c) {
    double aa = fabs(a);
    // Cody-Waite (accurate for |a| < 1e6)
    double kd = rint(a * 0.15915494309189535);
    double r  = fma(-kd, 6.283185307179586, a);
    r         = fma(-kd, 2.4492935982947064e-16, r);
    // Payne-Hanek (for |a| >= 1e6); index clamped so unselected path is safe
    long long b = __double_as_longlong(aa);
    int E = (int)((unsigned long long)b >> 52);
    unsigned long long ix = ((unsigned long long)b & 0xFFFFFFFFFFFFFULL) | (1ULL << 52);
    int q = E - 1013; q = q < 0 ? 0 : q;
    int i = q >> 6, sh = q & 63;
    unsigned long long p0 = ph[i], p1 = ph[i+1], p2 = ph[i+2], p3 = ph[i+3];
    unsigned long long w0 = (p0 << sh) | ((p1 >> 1) >> (63 - sh));
    unsigned long long w1 = (p1 << sh) | ((p2 >> 1) >> (63 - sh));
    unsigned long long w2 = (p2 << sh) | ((p3 >> 1) >> (63 - sh));
    unsigned long long l0 = ix * w0;
    unsigned long long h1 = __umul64hi(ix, w1);
    unsigned long long l1 = ix * w1;
    unsigned long long h2 = __umul64hi(ix, w2);
    unsigned long long flo = l1 + h2;
    unsigned long long fhi = l0 + h1 + (flo < l1 ? 1ULL : 0ULL);
    double fr  = (double)(long long)fhi * 5.421010862427522e-20;   // [-0.5, 0.5)
    double ang = fr * 6.283185307179586;
    ang = (a < 0.0) ? -ang : ang;
    float rf = (aa < 1.0e6) ? (float)r : (float)ang;
    float sf, cf;
    __sincosf(rf, &sf, &cf);
    s = (double)sf; c = (double)cf;
}

// ---------------------------------------------------------------------------
// Prep: dtype detect, softmaxes, bypass-fold gates, fold leaves into round-0,
// emit float4/double split tables.
// ---------------------------------------------------------------------------
__global__ void prep_kernel(const void* __restrict__ leafv,
                            const void* __restrict__ gatev,
                            float* __restrict__ out,
                            int tail_mode, long long tail_off) {
    __shared__ int    s_is_f32;
    __shared__ double s_w[N_LEAVES * 3];
    int t = threadIdx.x;

    if (t == 0) {
        const float* lf = (const float*)leafv;
        int cnt = 0;
        for (int i = 0; i < 64; ++i) {
            float v = fabsf(lf[i]);
            if (isfinite(v) && v > 1e-4f && v < 100.0f) ++cnt;
        }
        s_is_f32 = (cnt >= 52) ? 1 : 0;
    }
    __syncthreads();
    const int f32w = s_is_f32;
    const float*  lf = (const float*) leafv;
    const double* ld = (const double*)leafv;
    const float*  gf = (const float*) gatev;
    const double* gd = (const double*)gatev;

    if (t < N_LEAVES) {
        double a = f32w ? (double)lf[3*t]   : ld[3*t];
        double b = f32w ? (double)lf[3*t+1] : ld[3*t+1];
        double c = f32w ? (double)lf[3*t+2] : ld[3*t+2];
        double m = fmax(a, fmax(b, c));
        double ea = exp(a - m), eb = exp(b - m), ec = exp(c - m);
        double inv = 1.0 / (ea + eb + ec);
        double w[3] = {ea*inv, eb*inv, ec*inv};
        for (int j = 0; j < 3; ++j) {
            s_w[3*t+j] = w[j];
            if (tail_mode == 1) out[tail_off + 3*t + j] = (float)w[j];
        }
    } else if (t < N_LEAVES + 2*N_INTERNAL) {
        int g = t - N_LEAVES;                      // 0..125
        double v0 = f32w ? (double)gf[4*g]   : gd[4*g];
        double v1 = f32w ? (double)gf[4*g+1] : gd[4*g+1];
        double v2 = f32w ? (double)gf[4*g+2] : gd[4*g+2];
        double v3 = f32w ? (double)gf[4*g+3] : gd[4*g+3];
        double m = fmax(fmax(v0, v1), fmax(v2, v3));
        double e0 = exp(v0-m), e1 = exp(v1-m), e2 = exp(v2-m), e3 = exp(v3-m);
        double inv = 1.0 / (e0 + e1 + e2 + e3);
        double p0 = e0*inv, p1 = e1*inv, p2 = e2*inv, p3 = e3*inv;
        if (tail_mode == 1) {
            out[tail_off + 3*N_LEAVES + 4*g]   = (float)p0;
            out[tail_off + 3*N_LEAVES + 4*g+1] = (float)p1;
            out[tail_off + 3*N_LEAVES + 4*g+2] = (float)p2;
            out[tail_off + 3*N_LEAVES + 4*g+3] = (float)p3;
        }
        // Fold bypass (reference priority order) + child mask:
        if (p0 > BYPASS_TH) { p0 = 1.0; p1 = 0.0; p2 = 0.0; p3 = 0.0; }
        if (p1 > BYPASS_TH) { p0 = 0.0; p1 = 1.0; p2 = 0.0; p3 = 0.0; }
        if (p2 > BYPASS_TH) { p0 = 0.0; p1 = 0.0; p2 = 1.0; p3 = 0.0; }
        if (!(p3 > CHILD_EPS)) p3 = 0.0;
        g_g[4*g]   = p0; g_g[4*g+1] = p1; g_g[4*g+2] = p2; g_g[4*g+3] = p3;
        g_gf4[g]   = make_float4((float)p0, (float)p1, (float)p2, 0.0f);
        g_gp3[g]   = p3;
    }
    __syncthreads();

    // Round-0 fold: leaf t feeds gate row t>>1, side t&1.
    if (t < N_LEAVES) {
        const double* gp = &g_g[(t >> 1) * 8 + (t & 1) * 4];
        double c0 = gp[0] + gp[3] * s_w[3*t];
        double c1 = gp[1] + gp[3] * s_w[3*t+1];
        double c2 = gp[2] + gp[3] * s_w[3*t+2];
        g_r0f[t] = make_float4((float)c0, (float)c1, (float)c2, 0.0f);
    }
}

// ---------------------------------------------------------------------------
// One internal node: (left, right) children -> clamp(exp(bL) - log(bR)).
// ---------------------------------------------------------------------------
__device__ __forceinline__ void eval_node(const float4* __restrict__ sf4,
                                          const double* __restrict__ sp3,
                                          int node,
                                          const unsigned long long* __restrict__ ph,
                                          double clr, double cli,
                                          double crr, double cri,
                                          float x0f, float x1f,
                                          double& olr, double& oli) {
    float4 L = sf4[2*node], R = sf4[2*node+1];
    double p3l = sp3[2*node], p3r = sp3[2*node+1];
    float basel = fmaf(L.y, x0f, fmaf(L.z, x1f, L.x));
    float baser = fmaf(R.y, x0f, fmaf(R.z, x1f, R.x));
    double alr = fma(p3l, clr, (double)basel);
    double ali = p3l * cli;
    double brr = fma(p3r, crr, (double)baser);
    double bri = p3r * cri;
    double ea = fast_exp(alr);
    double s, c;
    fast_sincos(ph, ali, s, c);
    double gr, gi;
    fast_clog(brr, bri, gr, gi);
    olr = clampd(fma(ea, c, -gr));
    oli = clampd(fma(ea, s, -gi));
}

// ---------------------------------------------------------------------------
// Main kernel: 4 lanes per element; lane-local through round 3, shfl after.
// ---------------------------------------------------------------------------
__global__ __launch_bounds__(128)
void tree_kernel(const float* __restrict__ x, float* __restrict__ out,
                 int interleaved) {
    __shared__ float4 sr0[N_LEAVES];
    __shared__ float4 sf4[126];
    __shared__ double sp3[126];
    __shared__ unsigned long long sph[21];
    int tid = threadIdx.x;
    for (int i = tid; i < N_LEAVES; i += 128) sr0[i] = g_r0f[i];
    for (int i = tid; i < 126; i += 128)      { sf4[i] = g_gf4[i]; sp3[i] = g_gp3[i]; }
    if (tid < 21) sph[tid] = PH_TAB[tid];
    __syncthreads();

    int g    = blockIdx.x * 128 + tid;
    int e    = g >> 2;
    int lane = g & 3;

    float x0f = x[2*e];
    float x1f = x[2*e+1];

    double lr[8], li[8];

    // Round 0: 8 real pairs for this lane (leaves 16*lane .. 16*lane+15).
#pragma unroll
    for (int k = 0; k < 8; ++k) {
        int gk = 8*lane + k;
        float4 L = sr0[2*gk], R = sr0[2*gk+1];
        float bl = fmaf(L.y, x0f, fmaf(L.z, x1f, L.x));
        float br = fmaf(R.y, x0f, fmaf(R.z, x1f, R.x));
        double er = fast_exp((double)bl);
        double gr = (double)__log2f(fabsf(br)) * LN2_D;
        lr[k] = clampd(er - gr);
        li[k] = signbit(br) ? -PI_D : 0.0;
    }

    // Round 1: gate rows 32 + 4*lane + j.
#pragma unroll
    for (int j = 0; j < 4; ++j)
        eval_node(sf4, sp3, 32 + 4*lane + j, sph,
                  lr[2*j], li[2*j], lr[2*j+1], li[2*j+1], x0f, x1f, lr[j], li[j]);

    // Round 2: gate rows 48 + 2*lane + j.
#pragma unroll
    for (int j = 0; j < 2; ++j)
        eval_node(sf4, sp3, 48 + 2*lane + j, sph,
                  lr[2*j], li[2*j], lr[2*j+1], li[2*j+1], x0f, x1f, lr[j], li[j]);

    // Round 3: gate row 56 + lane.
    eval_node(sf4, sp3, 56 + lane, sph,
              lr[0], li[0], lr[1], li[1], x0f, x1f, lr[0], li[0]);

    // Round 4: pair (0,1) on lane 0, (2,3) on lane 2.
    {
        double pr = __shfl_xor_sync(0xffffffffu, lr[0], 1);
        double pi = __shfl_xor_sync(0xffffffffu, li[0], 1);
        eval_node(sf4, sp3, 60 + (lane >> 1), sph,
                  lr[0], li[0], pr, pi, x0f, x1f, lr[0], li[0]);
    }

    // Round 5: pair on lane 0 (right child from lane 2).
    {
        double pr = __shfl_xor_sync(0xffffffffu, lr[0], 2);
        double pi = __shfl_xor_sync(0xffffffffu, li[0], 2);
        eval_node(sf4, sp3, 62, sph,
                  lr[0], li[0], pr, pi, x0f, x1f, lr[0], li[0]);
    }

    if (lane == 0) {
        if (interleaved) {
            out[2*e]   = (float)lr[0];
            out[2*e+1] = (float)li[0];
        } else {
            out[e] = (float)lr[0];
        }
    }
}

// ---------------------------------------------------------------------------
extern "C" void kernel_launch(void* const* d_in, const int* in_sizes, int n_in,
                              void* d_out, int out_size) {
    const float* x    = nullptr;
    const void*  leaf = nullptr;
    const void*  gate = nullptr;
    for (int i = 0; i < n_in; ++i) {
        if      (in_sizes[i] == 2 * BATCH)      x    = (const float*)d_in[i];
        else if (in_sizes[i] == 3 * N_LEAVES)   leaf = d_in[i];
        else if (in_sizes[i] == 8 * N_INTERNAL) gate = d_in[i];
    }
    if (!x || !leaf || !gate) return;

    float* out = (float*)d_out;

    const int NPROB = 3*N_LEAVES + 8*N_INTERNAL;  // 696
    int interleaved, tail_mode = 0;
    long long tail_off = 0;

    if (out_size >= 2*BATCH + NPROB) {
        interleaved = 1; tail_mode = 1; tail_off = 2*BATCH;
    } else if (out_size >= 2*BATCH) {
        interleaved = 1;
    } else if (out_size >= BATCH + NPROB) {
        interleaved = 0; tail_mode = 1; tail_off = BATCH;
    } else {
        interleaved = 0;
    }

    prep_kernel<<<1, 192>>>(leaf, gate, out, tail_mode, tail_off);
    tree_kernel<<<(BATCH*4)/128, 128>>>(x, out, interleaved);
}

// round 11
// speedup vs baseline: 1.2820x; 1.2820x over previous
#include <cuda_runtime.h>
#include <math.h>

#define BATCH      262144
#define N_LEAVES   64
#define N_INTERNAL 63

#define CHILD_EPS  2.2204460492503131e-16
#define BYPASS_TH  0.9999999999999998   /* 1 - DBL_EPSILON */
#define CLAMP_V    1e300
#define PI_D       3.141592653589793
#define LN2_D      0.6931471805599453

// Folded parameters (built by prep kernel).
static __device__ double g_g  [N_INTERNAL * 8];  // folded gates (double, for fold step)
static __device__ float4 g_gf4[126];             // per side: (p0,p1,p2,0) as float
static __device__ double g_gp3[126];             // per side: p3 (double)
static __device__ float4 g_r0f[N_LEAVES];        // round-0 folded coeffs per leaf

// 2/pi fraction bits (fdlibm two_over_pi), prepended zero word.
static __device__ const unsigned long long PH_TAB[21] = {
    0x0000000000000000ULL,
    0xA2F9836E4E441529ULL, 0xFC2757D1F534DDC0ULL, 0xDB6295993C439041ULL,
    0xFE5163ABDEBBC561ULL, 0xB7246E3A424DD2E0ULL, 0x06492EEA09D1921CULL,
    0xFE1DEB1CB129A73EULL, 0xE88235F52EBB4484ULL, 0xE99C7026B45F7E41ULL,
    0x3991D639835339F4ULL, 0x9C845F8BBDF9283BULL, 0x1FF897FFDE05980FULL,
    0xEF2F118B5A0A6D1FULL, 0x6D367ECF27CB09B7ULL, 0x4F463F669E5FEA2DULL,
    0x7527BAC7EBE5F17BULL, 0x3D0739F78A5292EAULL, 0x6BFB5FB11F8D5D08ULL,
    0x56033046FC7B6BABULL, 0xF0CFBC209AF4361DULL
};

__device__ __forceinline__ double clampd(double v) {
    double r = fmin(fmax(v, -CLAMP_V), CLAMP_V);
    return (v != v) ? 0.0 : r;     // inf*0 corner -> 0 like reference nan_to_num
}

// Branchless double-range exp with fp32 core.
__device__ __forceinline__ double fast_exp(double a) {
    double ac = fmin(fmax(a, -746.0), 710.0);
    double kd = rint(ac * 1.4426950408889634);
    double r  = fma(-kd, 0.6931471805599453, ac);
    r         = fma(-kd, 2.3190468138462996e-17, r);
    int k  = (int)kd;
    int k1 = k >> 1, k2 = k - k1;
    double s1 = __longlong_as_double((long long)(k1 + 1023) << 52);
    double s2 = __longlong_as_double((long long)(k2 + 1023) << 52);
    return ((double)__expf((float)r) * s1) * s2;
}

// complex log, fp32 core after 2^k scaling.
__device__ __forceinline__ void fast_clog(double x, double y, double& lr_, double& li_) {
    long long bx = __double_as_longlong(x) & 0x7fffffffffffffffLL;
    long long by = __double_as_longlong(y) & 0x7fffffffffffffffLL;
    int ex = (int)(bx >> 52), ey = (int)(by >> 52);
    int em = ex > ey ? ex : ey;
    int k  = 1022 - em;
    double s = (k >= -1022)
        ? __longlong_as_double((long long)(k + 1023) << 52)
        : __longlong_as_double((long long)(23) << 52)                 // 2^-1000
          * __longlong_as_double((long long)(k + 1000 + 1023) << 52);
    float xsf = (float)(x * s), ysf = (float)(y * s);
    float m2  = fmaf(xsf, xsf, ysf * ysf);
    lr_ = (0.5 * (double)__log2f(m2) + (double)(em - 1022)) * LN2_D;
    li_ = (double)atan2f(ysf, xsf);
}

// Branchy sincos: cheap Cody-Waite path; Payne-Hanek only when |a| >= 1e6.
__device__ __forceinline__ void fast_sincos(const unsigned long long* __restrict__ ph,
                                            double a, double& s, double& c) {
    float sf, cf;
    double aa = fabs(a);
    if (aa < 1.0e6) {
        double kd = rint(a * 0.15915494309189535);
        double r  = fma(-kd, 6.283185307179586, a);
        r         = fma(-kd, 2.4492935982947064e-16, r);
        __sincosf((float)r, &sf, &cf);
    } else {
        long long b = __double_as_longlong(aa);
        int E = (int)((unsigned long long)b >> 52);
        unsigned long long ix = ((unsigned long long)b & 0xFFFFFFFFFFFFFULL) | (1ULL << 52);
        int q = E - 1013;
        int i = q >> 6, sh = q & 63;
        unsigned long long p0 = ph[i], p1 = ph[i+1], p2 = ph[i+2], p3 = ph[i+3];
        unsigned long long w0 = (p0 << sh) | ((p1 >> 1) >> (63 - sh));
        unsigned long long w1 = (p1 << sh) | ((p2 >> 1) >> (63 - sh));
        unsigned long long w2 = (p2 << sh) | ((p3 >> 1) >> (63 - sh));
        unsigned long long l0 = ix * w0;
        unsigned long long h1 = __umul64hi(ix, w1);
        unsigned long long l1 = ix * w1;
        unsigned long long h2 = __umul64hi(ix, w2);
        unsigned long long flo = l1 + h2;
        unsigned long long fhi = l0 + h1 + (flo < l1 ? 1ULL : 0ULL);
        double fr  = (double)(long long)fhi * 5.421010862427522e-20;   // [-0.5,0.5)
        double ang = fr * 6.283185307179586;
        __sincosf((float)ang, &sf, &cf);
        sf = (a < 0.0) ? -sf : sf;
    }
    s = (double)sf; c = (double)cf;
}

// ---------------------------------------------------------------------------
// Prep: dtype detect, softmaxes, bypass-fold gates, fold leaves into round-0,
// emit float4/double split tables.
// ---------------------------------------------------------------------------
__global__ void prep_kernel(const void* __restrict__ leafv,
                            const void* __restrict__ gatev,
                            float* __restrict__ out,
                            int tail_mode, long long tail_off) {
    __shared__ int    s_is_f32;
    __shared__ double s_w[N_LEAVES * 3];
    int t = threadIdx.x;

    if (t == 0) {
        const float* lf = (const float*)leafv;
        int cnt = 0;
        for (int i = 0; i < 64; ++i) {
            float v = fabsf(lf[i]);
            if (isfinite(v) && v > 1e-4f && v < 100.0f) ++cnt;
        }
        s_is_f32 = (cnt >= 52) ? 1 : 0;
    }
    __syncthreads();
    const int f32w = s_is_f32;
    const float*  lf = (const float*) leafv;
    const double* ld = (const double*)leafv;
    const float*  gf = (const float*) gatev;
    const double* gd = (const double*)gatev;

    if (t < N_LEAVES) {
        double a = f32w ? (double)lf[3*t]   : ld[3*t];
        double b = f32w ? (double)lf[3*t+1] : ld[3*t+1];
        double c = f32w ? (double)lf[3*t+2] : ld[3*t+2];
        double m = fmax(a, fmax(b, c));
        double ea = exp(a - m), eb = exp(b - m), ec = exp(c - m);
        double inv = 1.0 / (ea + eb + ec);
        double w[3] = {ea*inv, eb*inv, ec*inv};
        for (int j = 0; j < 3; ++j) {
            s_w[3*t+j] = w[j];
            if (tail_mode == 1) out[tail_off + 3*t + j] = (float)w[j];
        }
    } else if (t < N_LEAVES + 2*N_INTERNAL) {
        int g = t - N_LEAVES;                      // 0..125
        double v0 = f32w ? (double)gf[4*g]   : gd[4*g];
        double v1 = f32w ? (double)gf[4*g+1] : gd[4*g+1];
        double v2 = f32w ? (double)gf[4*g+2] : gd[4*g+2];
        double v3 = f32w ? (double)gf[4*g+3] : gd[4*g+3];
        double m = fmax(fmax(v0, v1), fmax(v2, v3));
        double e0 = exp(v0-m), e1 = exp(v1-m), e2 = exp(v2-m), e3 = exp(v3-m);
        double inv = 1.0 / (e0 + e1 + e2 + e3);
        double p0 = e0*inv, p1 = e1*inv, p2 = e2*inv, p3 = e3*inv;
        if (tail_mode == 1) {
            out[tail_off + 3*N_LEAVES + 4*g]   = (float)p0;
            out[tail_off + 3*N_LEAVES + 4*g+1] = (float)p1;
            out[tail_off + 3*N_LEAVES + 4*g+2] = (float)p2;
            out[tail_off + 3*N_LEAVES + 4*g+3] = (float)p3;
        }
        if (p0 > BYPASS_TH) { p0 = 1.0; p1 = 0.0; p2 = 0.0; p3 = 0.0; }
        if (p1 > BYPASS_TH) { p0 = 0.0; p1 = 1.0; p2 = 0.0; p3 = 0.0; }
        if (p2 > BYPASS_TH) { p0 = 0.0; p1 = 0.0; p2 = 1.0; p3 = 0.0; }
        if (!(p3 > CHILD_EPS)) p3 = 0.0;
        g_g[4*g]   = p0; g_g[4*g+1] = p1; g_g[4*g+2] = p2; g_g[4*g+3] = p3;
        g_gf4[g]   = make_float4((float)p0, (float)p1, (float)p2, 0.0f);
        g_gp3[g]   = p3;
    }
    __syncthreads();

    if (t < N_LEAVES) {
        const double* gp = &g_g[(t >> 1) * 8 + (t & 1) * 4];
        double c0 = gp[0] + gp[3] * s_w[3*t];
        double c1 = gp[1] + gp[3] * s_w[3*t+1];
        double c2 = gp[2] + gp[3] * s_w[3*t+2];
        g_r0f[t] = make_float4((float)c0, (float)c1, (float)c2, 0.0f);
    }
}

// ---------------------------------------------------------------------------
// Node eval. SmallAngle=true: |p3*cli| <= pi guaranteed -> direct __sincosf.
// ---------------------------------------------------------------------------
template <bool SmallAngle>
__device__ __forceinline__ void eval_node(const float4* __restrict__ sf4,
                                          const double* __restrict__ sp3,
                                          int node,
                                          const unsigned long long* __restrict__ ph,
                                          double clr, double cli,
                                          double crr, double cri,
                                          float x0f, float x1f,
                                          double& olr, double& oli) {
    float4 L = sf4[2*node], R = sf4[2*node+1];
    double p3l = sp3[2*node], p3r = sp3[2*node+1];
    float basel = fmaf(L.y, x0f, fmaf(L.z, x1f, L.x));
    float baser = fmaf(R.y, x0f, fmaf(R.z, x1f, R.x));
    double alr = fma(p3l, clr, (double)basel);
    double ali = p3l * cli;
    double brr = fma(p3r, crr, (double)baser);
    double bri = p3r * cri;
    double ea = fast_exp(alr);
    double s, c;
    if (SmallAngle) {
        float sf, cf;
        __sincosf((float)ali, &sf, &cf);     // |ali| <= pi, no reduction needed
        s = (double)sf; c = (double)cf;
    } else {
        fast_sincos(ph, ali, s, c);
    }
    double gr, gi;
    fast_clog(brr, bri, gr, gi);
    olr = clampd(fma(ea, c, -gr));
    oli = clampd(fma(ea, s, -gi));
}

// ---------------------------------------------------------------------------
// Main kernel: 4 lanes per element; lane-local through round 3, shfl after.
// ---------------------------------------------------------------------------
__global__ __launch_bounds__(128)
void tree_kernel(const float* __restrict__ x, float* __restrict__ out,
                 int interleaved) {
    __shared__ float4 sr0[N_LEAVES];
    __shared__ float4 sf4[126];
    __shared__ double sp3[126];
    __shared__ unsigned long long sph[21];
    int tid = threadIdx.x;
    for (int i = tid; i < N_LEAVES; i += 128) sr0[i] = g_r0f[i];
    for (int i = tid; i < 126; i += 128)      { sf4[i] = g_gf4[i]; sp3[i] = g_gp3[i]; }
    if (tid < 21) sph[tid] = PH_TAB[tid];
    __syncthreads();

    int g    = blockIdx.x * 128 + tid;
    int e    = g >> 2;
    int lane = g & 3;

    float x0f = x[2*e];
    float x1f = x[2*e+1];

    double lr[8], li[8];

    // Round 0: 8 real pairs for this lane.
#pragma unroll
    for (int k = 0; k < 8; ++k) {
        int gk = 8*lane + k;
        float4 L = sr0[2*gk], R = sr0[2*gk+1];
        float bl = fmaf(L.y, x0f, fmaf(L.z, x1f, L.x));
        float br = fmaf(R.y, x0f, fmaf(R.z, x1f, R.x));
        double er = fast_exp((double)bl);
        double gr = (double)__log2f(fabsf(br)) * LN2_D;
        lr[k] = clampd(er - gr);
        li[k] = signbit(br) ? -PI_D : 0.0;
    }

    // Round 1: angles are p3 * {0, -pi} -> |ali| <= pi, small-angle fast path.
#pragma unroll
    for (int j = 0; j < 4; ++j)
        eval_node<true>(sf4, sp3, 32 + 4*lane + j, sph,
                        lr[2*j], li[2*j], lr[2*j+1], li[2*j+1], x0f, x1f, lr[j], li[j]);

    // Round 2: full-range.
#pragma unroll
    for (int j = 0; j < 2; ++j)
        eval_node<false>(sf4, sp3, 48 + 2*lane + j, sph,
                         lr[2*j], li[2*j], lr[2*j+1], li[2*j+1], x0f, x1f, lr[j], li[j]);

    // Round 3.
    eval_node<false>(sf4, sp3, 56 + lane, sph,
                     lr[0], li[0], lr[1], li[1], x0f, x1f, lr[0], li[0]);

    // Round 4: pair (0,1) on lane 0, (2,3) on lane 2.
    {
        double pr = __shfl_xor_sync(0xffffffffu, lr[0], 1);
        double pi = __shfl_xor_sync(0xffffffffu, li[0], 1);
        eval_node<false>(sf4, sp3, 60 + (lane >> 1), sph,
                         lr[0], li[0], pr, pi, x0f, x1f, lr[0], li[0]);
    }

    // Round 5: pair on lane 0 (right child from lane 2).
    {
        double pr = __shfl_xor_sync(0xffffffffu, lr[0], 2);
        double pi = __shfl_xor_sync(0xffffffffu, li[0], 2);
        eval_node<false>(sf4, sp3, 62, sph,
                         lr[0], li[0], pr, pi, x0f, x1f, lr[0], li[0]);
    }

    if (lane == 0) {
        if (interleaved) {
            out[2*e]   = (float)lr[0];
            out[2*e+1] = (float)li[0];
        } else {
            out[e] = (float)lr[0];
        }
    }
}

// ---------------------------------------------------------------------------
extern "C" void kernel_launch(void* const* d_in, const int* in_sizes, int n_in,
                              void* d_out, int out_size) {
    const float* x    = nullptr;
    const void*  leaf = nullptr;
    const void*  gate = nullptr;
    for (int i = 0; i < n_in; ++i) {
        if      (in_sizes[i] == 2 * BATCH)      x    = (const float*)d_in[i];
        else if (in_sizes[i] == 3 * N_LEAVES)   leaf = d_in[i];
        else if (in_sizes[i] == 8 * N_INTERNAL) gate = d_in[i];
    }
    if (!x || !leaf || !gate) return;

    float* out = (float*)d_out;

    const int NPROB = 3*N_LEAVES + 8*N_INTERNAL;  // 696
    int interleaved, tail_mode = 0;
    long long tail_off = 0;

    if (out_size >= 2*BATCH + NPROB) {
        interleaved = 1; tail_mode = 1; tail_off = 2*BATCH;
    } else if (out_size >= 2*BATCH) {
        interleaved = 1;
    } else if (out_size >= BATCH + NPROB) {
        interleaved = 0; tail_mode = 1; tail_off = BATCH;
    } else {
        interleaved = 0;
    }

    prep_kernel<<<1, 192>>>(leaf, gate, out, tail_mode, tail_off);
    tree_kernel<<<(BATCH*4)/128, 128>>>(x, out, interleaved);
}

// round 12
// speedup vs baseline: 1.6176x; 1.2617x over previous
#include <cuda_runtime.h>
#include <math.h>

#define BATCH      262144
#define N_LEAVES   64
#define N_INTERNAL 63

#define CHILD_EPS  2.2204460492503131e-16
#define BYPASS_TH  0.9999999999999998   /* 1 - DBL_EPSILON */
#define CLAMP_V    1e300
#define PI_F       3.14159265358979f
#define LN2_F      0.69314718056f
#define LN2_D      0.6931471805599453

// Folded parameters (built by prep kernel).
static __device__ double g_g  [N_INTERNAL * 8];  // folded gates (double, for fold step)
static __device__ float4 g_gf4[126];             // per side: (p0,p1,p2,p3) as float
static __device__ double g_gp3[126];             // per side: p3 (double)
static __device__ float4 g_r0f[N_LEAVES];        // round-0 folded coeffs per leaf

// 2/pi fraction bits (fdlibm two_over_pi), prepended zero word.
static __device__ const unsigned long long PH_TAB[21] = {
    0x0000000000000000ULL,
    0xA2F9836E4E441529ULL, 0xFC2757D1F534DDC0ULL, 0xDB6295993C439041ULL,
    0xFE5163ABDEBBC561ULL, 0xB7246E3A424DD2E0ULL, 0x06492EEA09D1921CULL,
    0xFE1DEB1CB129A73EULL, 0xE88235F52EBB4484ULL, 0xE99C7026B45F7E41ULL,
    0x3991D639835339F4ULL, 0x9C845F8BBDF9283BULL, 0x1FF897FFDE05980FULL,
    0xEF2F118B5A0A6D1FULL, 0x6D367ECF27CB09B7ULL, 0x4F463F669E5FEA2DULL,
    0x7527BAC7EBE5F17BULL, 0x3D0739F78A5292EAULL, 0x6BFB5FB11F8D5D08ULL,
    0x56033046FC7B6BABULL, 0xF0CFBC209AF4361DULL
};

__device__ __forceinline__ double clampd(double v) {
    double r = fmin(fmax(v, -CLAMP_V), CLAMP_V);
    return (v != v) ? 0.0 : r;     // inf*0 corner -> 0 like reference nan_to_num
}

// Branchy sincos (float outputs): Cody-Waite (<1e6) or Payne-Hanek.
__device__ __forceinline__ void fast_sincos(const unsigned long long* __restrict__ ph,
                                            double a, float& sf, float& cf) {
    double aa = fabs(a);
    if (aa < 1.0e6) {
        double kd = rint(a * 0.15915494309189535);
        double r  = fma(-kd, 6.283185307179586, a);
        r         = fma(-kd, 2.4492935982947064e-16, r);
        __sincosf((float)r, &sf, &cf);
    } else {
        long long b = __double_as_longlong(aa);
        int E = (int)((unsigned long long)b >> 52);
        unsigned long long ix = ((unsigned long long)b & 0xFFFFFFFFFFFFFULL) | (1ULL << 52);
        int q = E - 1013;
        int i = q >> 6, sh = q & 63;
        unsigned long long p0 = ph[i], p1 = ph[i+1], p2 = ph[i+2], p3 = ph[i+3];
        unsigned long long w0 = (p0 << sh) | ((p1 >> 1) >> (63 - sh));
        unsigned long long w1 = (p1 << sh) | ((p2 >> 1) >> (63 - sh));
        unsigned long long w2 = (p2 << sh) | ((p3 >> 1) >> (63 - sh));
        unsigned long long l0 = ix * w0;
        unsigned long long h1 = __umul64hi(ix, w1);
        unsigned long long l1 = ix * w1;
        unsigned long long h2 = __umul64hi(ix, w2);
        unsigned long long flo = l1 + h2;
        unsigned long long fhi = l0 + h1 + (flo < l1 ? 1ULL : 0ULL);
        double fr  = (double)(long long)fhi * 5.421010862427522e-20;   // [-0.5,0.5)
        double ang = fr * 6.283185307179586;
        __sincosf((float)ang, &sf, &cf);
        sf = (a < 0.0) ? -sf : sf;
    }
}

// ---------------------------------------------------------------------------
// Prep: dtype detect, softmaxes, bypass-fold gates, fold leaves into round-0.
// ---------------------------------------------------------------------------
__global__ void prep_kernel(const void* __restrict__ leafv,
                            const void* __restrict__ gatev,
                            float* __restrict__ out,
                            int tail_mode, long long tail_off) {
    __shared__ int    s_is_f32;
    __shared__ double s_w[N_LEAVES * 3];
    int t = threadIdx.x;

    if (t == 0) {
        const float* lf = (const float*)leafv;
        int cnt = 0;
        for (int i = 0; i < 64; ++i) {
            float v = fabsf(lf[i]);
            if (isfinite(v) && v > 1e-4f && v < 100.0f) ++cnt;
        }
        s_is_f32 = (cnt >= 52) ? 1 : 0;
    }
    __syncthreads();
    const int f32w = s_is_f32;
    const float*  lf = (const float*) leafv;
    const double* ld = (const double*)leafv;
    const float*  gf = (const float*) gatev;
    const double* gd = (const double*)gatev;

    if (t < N_LEAVES) {
        double a = f32w ? (double)lf[3*t]   : ld[3*t];
        double b = f32w ? (double)lf[3*t+1] : ld[3*t+1];
        double c = f32w ? (double)lf[3*t+2] : ld[3*t+2];
        double m = fmax(a, fmax(b, c));
        double ea = exp(a - m), eb = exp(b - m), ec = exp(c - m);
        double inv = 1.0 / (ea + eb + ec);
        double w[3] = {ea*inv, eb*inv, ec*inv};
        for (int j = 0; j < 3; ++j) {
            s_w[3*t+j] = w[j];
            if (tail_mode == 1) out[tail_off + 3*t + j] = (float)w[j];
        }
    } else if (t < N_LEAVES + 2*N_INTERNAL) {
        int g = t - N_LEAVES;                      // 0..125
        double v0 = f32w ? (double)gf[4*g]   : gd[4*g];
        double v1 = f32w ? (double)gf[4*g+1] : gd[4*g+1];
        double v2 = f32w ? (double)gf[4*g+2] : gd[4*g+2];
        double v3 = f32w ? (double)gf[4*g+3] : gd[4*g+3];
        double m = fmax(fmax(v0, v1), fmax(v2, v3));
        double e0 = exp(v0-m), e1 = exp(v1-m), e2 = exp(v2-m), e3 = exp(v3-m);
        double inv = 1.0 / (e0 + e1 + e2 + e3);
        double p0 = e0*inv, p1 = e1*inv, p2 = e2*inv, p3 = e3*inv;
        if (tail_mode == 1) {
            out[tail_off + 3*N_LEAVES + 4*g]   = (float)p0;
            out[tail_off + 3*N_LEAVES + 4*g+1] = (float)p1;
            out[tail_off + 3*N_LEAVES + 4*g+2] = (float)p2;
            out[tail_off + 3*N_LEAVES + 4*g+3] = (float)p3;
        }
        if (p0 > BYPASS_TH) { p0 = 1.0; p1 = 0.0; p2 = 0.0; p3 = 0.0; }
        if (p1 > BYPASS_TH) { p0 = 0.0; p1 = 1.0; p2 = 0.0; p3 = 0.0; }
        if (p2 > BYPASS_TH) { p0 = 0.0; p1 = 0.0; p2 = 1.0; p3 = 0.0; }
        if (!(p3 > CHILD_EPS)) p3 = 0.0;
        g_g[4*g]   = p0; g_g[4*g+1] = p1; g_g[4*g+2] = p2; g_g[4*g+3] = p3;
        g_gf4[g]   = make_float4((float)p0, (float)p1, (float)p2, (float)p3);
        g_gp3[g]   = p3;
    }
    __syncthreads();

    if (t < N_LEAVES) {
        const double* gp = &g_g[(t >> 1) * 8 + (t & 1) * 4];
        double c0 = gp[0] + gp[3] * s_w[3*t];
        double c1 = gp[1] + gp[3] * s_w[3*t+1];
        double c2 = gp[2] + gp[3] * s_w[3*t+2];
        g_r0f[t] = make_float4((float)c0, (float)c1, (float)c2, 0.0f);
    }
}

// ---------------------------------------------------------------------------
// Round-1 node: children are fp32 (|re| <= ~2e11, im in {0,-pi}). All-fp32
// front-end; only the final 2^(k-1) scale is fp64.
// ---------------------------------------------------------------------------
__device__ __forceinline__ void eval_node_r1(const float4* __restrict__ sf4,
                                             int node,
                                             float clrf, float clif,
                                             float crrf, float crif,
                                             float x0f, float x1f,
                                             double& olr, double& oli) {
    float4 L = sf4[2*node], R = sf4[2*node+1];
    float basel = fmaf(L.y, x0f, fmaf(L.z, x1f, L.x));
    float baser = fmaf(R.y, x0f, fmaf(R.z, x1f, R.x));
    float alr = fmaf(L.w, clrf, basel);
    float ali = L.w * clif;                         // |ali| <= pi
    float brr = fmaf(R.w, crrf, baser);
    float bri = R.w * crif;
    // exp(alr), fp32 Cody-Waite with split ln2 (hi exact to 12 bits):
    float ac  = fminf(fmaxf(alr, -708.0f), 709.7f);
    float kdf = rintf(ac * 1.44269504f);
    float rf  = fmaf(-kdf, 0.693115234375f, ac);
    rf        = fmaf(-kdf, 3.1946183e-5f, rf);
    float ef2 = exp2f(fmaf(rf, 1.44269504f, 1.0f));   // 2*e^rf
    double sden = __longlong_as_double((long long)((int)kdf - 1 + 1023) << 52);
    float sf, cf;
    __sincosf(ali, &sf, &cf);
    // log(brr + i*bri): m2 <= ~8e22 fits fp32, no scaling.
    float m2  = fmaxf(fmaf(brr, brr, bri * bri), 1.2e-38f);
    float grf = 0.5f * __log2f(m2) * LN2_F;
    float gif = atan2f(bri, brr);
    olr = clampd(fma((double)(ef2 * cf), sden, -(double)grf));
    oli = clampd(fma((double)(ef2 * sf), sden, -(double)gif));
}

// ---------------------------------------------------------------------------
// Full-range node (rounds 2-5): double blends; single-scale exp; fp32 clog
// epilogue; no subnormal-k branch (|inputs| <= 1.1e300 => k >= -998).
// ---------------------------------------------------------------------------
__device__ __forceinline__ void eval_node_full(const float4* __restrict__ sf4,
                                               const double* __restrict__ sp3,
                                               int node,
                                               const unsigned long long* __restrict__ ph,
                                               double clr, double cli,
                                               double crr, double cri,
                                               float x0f, float x1f,
                                               double& olr, double& oli) {
    float4 L = sf4[2*node], R = sf4[2*node+1];
    double p3l = sp3[2*node], p3r = sp3[2*node+1];
    float basel = fmaf(L.y, x0f, fmaf(L.z, x1f, L.x));
    float baser = fmaf(R.y, x0f, fmaf(R.z, x1f, R.x));
    double alr = fma(p3l, clr, (double)basel);
    double ali = p3l * cli;
    double brr = fma(p3r, crr, (double)baser);
    double bri = p3r * cri;
    // exp(alr): double CW reduction (accuracy), fp32 core, ONE fp64 scale.
    double ac = fmin(fmax(alr, -708.0), 709.7);
    double kd = rint(ac * 1.4426950408889634);
    double r  = fma(-kd, 0.6931471805599453, ac);
    r         = fma(-kd, 2.3190468138462996e-17, r);
    float ef2 = exp2f(fmaf((float)r, 1.44269504f, 1.0f));   // 2*e^r
    double sden = __longlong_as_double((long long)((int)kd - 1 + 1023) << 52);
    float sf, cf;
    fast_sincos(ph, ali, sf, cf);
    // clog with 2^k scaling; k in [-998, 1022] -> branchless construct.
    long long bx = __double_as_longlong(brr) & 0x7fffffffffffffffLL;
    long long by = __double_as_longlong(bri) & 0x7fffffffffffffffLL;
    int ex = (int)(bx >> 52), ey = (int)(by >> 52);
    int em = ex > ey ? ex : ey;
    double sc = __longlong_as_double((long long)(2045 - em) << 52);   // 2^(1022-em)
    float xsf = (float)(brr * sc), ysf = (float)(bri * sc);
    float m2  = fmaxf(fmaf(xsf, xsf, ysf * ysf), 1.2e-38f);
    float grf = fmaf(0.5f, __log2f(m2), (float)(em - 1022)) * LN2_F;
    float gif = atan2f(ysf, xsf);
    olr = clampd(fma((double)(ef2 * cf), sden, -(double)grf));
    oli = clampd(fma((double)(ef2 * sf), sden, -(double)gif));
}

// ---------------------------------------------------------------------------
// Main kernel: 4 lanes per element; lane-local through round 3, shfl after.
// ---------------------------------------------------------------------------
__global__ __launch_bounds__(128)
void tree_kernel(const float* __restrict__ x, float* __restrict__ out,
                 int interleaved) {
    __shared__ float4 sr0[N_LEAVES];
    __shared__ float4 sf4[126];
    __shared__ double sp3[126];
    __shared__ unsigned long long sph[21];
    int tid = threadIdx.x;
    for (int i = tid; i < N_LEAVES; i += 128) sr0[i] = g_r0f[i];
    for (int i = tid; i < 126; i += 128)      { sf4[i] = g_gf4[i]; sp3[i] = g_gp3[i]; }
    if (tid < 21) sph[tid] = PH_TAB[tid];
    __syncthreads();

    int g    = blockIdx.x * 128 + tid;
    int e    = g >> 2;
    int lane = g & 3;

    float x0f = x[2*e];
    float x1f = x[2*e+1];

    // Round 0: fully fp32. |bl| <= ~30 -> er <= ~2e11 fits float.
    float lrf[8], lif[8];
#pragma unroll
    for (int k = 0; k < 8; ++k) {
        int gk = 8*lane + k;
        float4 L = sr0[2*gk], R = sr0[2*gk+1];
        float bl = fmaf(L.y, x0f, fmaf(L.z, x1f, L.x));
        float br = fmaf(R.y, x0f, fmaf(R.z, x1f, R.x));
        float er = __expf(bl);
        float gr = __log2f(fmaxf(fabsf(br), 1e-30f)) * LN2_F;
        lrf[k] = er - gr;
        lif[k] = signbit(br) ? -PI_F : 0.0f;
    }

    // Round 1: fp32 front-end nodes; outputs become double.
    double lr[4], li[4];
#pragma unroll
    for (int j = 0; j < 4; ++j)
        eval_node_r1(sf4, 32 + 4*lane + j,
                     lrf[2*j], lif[2*j], lrf[2*j+1], lif[2*j+1],
                     x0f, x1f, lr[j], li[j]);

    // Round 2.
#pragma unroll
    for (int j = 0; j < 2; ++j)
        eval_node_full(sf4, sp3, 48 + 2*lane + j, sph,
                       lr[2*j], li[2*j], lr[2*j+1], li[2*j+1],
                       x0f, x1f, lr[j], li[j]);

    // Round 3.
    eval_node_full(sf4, sp3, 56 + lane, sph,
                   lr[0], li[0], lr[1], li[1], x0f, x1f, lr[0], li[0]);

    // Round 4: pair (0,1) on lane 0, (2,3) on lane 2.
    {
        double pr = __shfl_xor_sync(0xffffffffu, lr[0], 1);
        double pi = __shfl_xor_sync(0xffffffffu, li[0], 1);
        eval_node_full(sf4, sp3, 60 + (lane >> 1), sph,
                       lr[0], li[0], pr, pi, x0f, x1f, lr[0], li[0]);
    }

    // Round 5: pair on lane 0 (right child from lane 2).
    {
        double pr = __shfl_xor_sync(0xffffffffu, lr[0], 2);
        double pi = __shfl_xor_sync(0xffffffffu, li[0], 2);
        eval_node_full(sf4, sp3, 62, sph,
                       lr[0], li[0], pr, pi, x0f, x1f, lr[0], li[0]);
    }

    if (lane == 0) {
        if (interleaved) {
            out[2*e]   = (float)lr[0];
            out[2*e+1] = (float)li[0];
        } else {
            out[e] = (float)lr[0];
        }
    }
}

// ---------------------------------------------------------------------------
extern "C" void kernel_launch(void* const* d_in, const int* in_sizes, int n_in,
                              void* d_out, int out_size) {
    const float* x    = nullptr;
    const void*  leaf = nullptr;
    const void*  gate = nullptr;
    for (int i = 0; i < n_in; ++i) {
        if      (in_sizes[i] == 2 * BATCH)      x    = (const float*)d_in[i];
        else if (in_sizes[i] == 3 * N_LEAVES)   leaf = d_in[i];
        else if (in_sizes[i] == 8 * N_INTERNAL) gate = d_in[i];
    }
    if (!x || !leaf || !gate) return;

    float* out = (float*)d_out;

    const int NPROB = 3*N_LEAVES + 8*N_INTERNAL;  // 696
    int interleaved, tail_mode = 0;
    long long tail_off = 0;

    if (out_size >= 2*BATCH + NPROB) {
        interleaved = 1; tail_mode = 1; tail_off = 2*BATCH;
    } else if (out_size >= 2*BATCH) {
        interleaved = 1;
    } else if (out_size >= BATCH + NPROB) {
        interleaved = 0; tail_mode = 1; tail_off = BATCH;
    } else {
        interleaved = 0;
    }

    prep_kernel<<<1, 192>>>(leaf, gate, out, tail_mode, tail_off);
    tree_kernel<<<(BATCH*4)/128, 128>>>(x, out, interleaved);
}

// round 13
// speedup vs baseline: 1.6302x; 1.0078x over previous
#include <cuda_runtime.h>
#include <math.h>

#define BATCH      262144
#define N_LEAVES   64
#define N_INTERNAL 63

#define CHILD_EPS  2.2204460492503131e-16
#define BYPASS_TH  0.9999999999999998   /* 1 - DBL_EPSILON */
#define CLAMP_V    1e300
#define PI_F       3.14159265358979f
#define LN2_F      0.69314718056f

// Folded parameters (built by prep kernel).
static __device__ double g_g  [N_INTERNAL * 8];  // folded gates (double, for fold step)
static __device__ float4 g_gf4[126];             // per side: (p0,p1,p2,p3) as float
static __device__ float4 g_r0f[N_LEAVES];        // round-0 folded coeffs per leaf

// 2/pi fraction bits (fdlibm two_over_pi), prepended zero word.
static __device__ const unsigned long long PH_TAB[21] = {
    0x0000000000000000ULL,
    0xA2F9836E4E441529ULL, 0xFC2757D1F534DDC0ULL, 0xDB6295993C439041ULL,
    0xFE5163ABDEBBC561ULL, 0xB7246E3A424DD2E0ULL, 0x06492EEA09D1921CULL,
    0xFE1DEB1CB129A73EULL, 0xE88235F52EBB4484ULL, 0xE99C7026B45F7E41ULL,
    0x3991D639835339F4ULL, 0x9C845F8BBDF9283BULL, 0x1FF897FFDE05980FULL,
    0xEF2F118B5A0A6D1FULL, 0x6D367ECF27CB09B7ULL, 0x4F463F669E5FEA2DULL,
    0x7527BAC7EBE5F17BULL, 0x3D0739F78A5292EAULL, 0x6BFB5FB11F8D5D08ULL,
    0x56033046FC7B6BABULL, 0xF0CFBC209AF4361DULL
};

// NaN is unreachable post-round-0 (gr always finite, er*sden finite-or-inf,
// no inf-inf / 0*inf), so a pure min/max clamp matches nan_to_num+clip.
__device__ __forceinline__ double clampd(double v) {
    return fmin(fmax(v, -CLAMP_V), CLAMP_V);
}

// Branchy sincos (float outputs): Cody-Waite (<1e6) or Payne-Hanek.
__device__ __forceinline__ void fast_sincos(const unsigned long long* __restrict__ ph,
                                            double a, float& sf, float& cf) {
    double aa = fabs(a);
    if (aa < 1.0e6) {
        double kd = rint(a * 0.15915494309189535);
        double r  = fma(-kd, 6.283185307179586, a);
        r         = fma(-kd, 2.4492935982947064e-16, r);
        __sincosf((float)r, &sf, &cf);
    } else {
        long long b = __double_as_longlong(aa);
        int E = (int)((unsigned long long)b >> 52);
        unsigned long long ix = ((unsigned long long)b & 0xFFFFFFFFFFFFFULL) | (1ULL << 52);
        int q = E - 1013;
        int i = q >> 6, sh = q & 63;
        unsigned long long p0 = ph[i], p1 = ph[i+1], p2 = ph[i+2], p3 = ph[i+3];
        unsigned long long w0 = (p0 << sh) | ((p1 >> 1) >> (63 - sh));
        unsigned long long w1 = (p1 << sh) | ((p2 >> 1) >> (63 - sh));
        unsigned long long w2 = (p2 << sh) | ((p3 >> 1) >> (63 - sh));
        unsigned long long l0 = ix * w0;
        unsigned long long h1 = __umul64hi(ix, w1);
        unsigned long long l1 = ix * w1;
        unsigned long long h2 = __umul64hi(ix, w2);
        unsigned long long flo = l1 + h2;
        unsigned long long fhi = l0 + h1 + (flo < l1 ? 1ULL : 0ULL);
        double fr  = (double)(long long)fhi * 5.421010862427522e-20;   // [-0.5,0.5)
        double ang = fr * 6.283185307179586;
        __sincosf((float)ang, &sf, &cf);
        sf = (a < 0.0) ? -sf : sf;
    }
}

// ---------------------------------------------------------------------------
// Prep: dtype detect, softmaxes, bypass-fold gates, fold leaves into round-0.
// ---------------------------------------------------------------------------
__global__ void prep_kernel(const void* __restrict__ leafv,
                            const void* __restrict__ gatev,
                            float* __restrict__ out,
                            int tail_mode, long long tail_off) {
    __shared__ int    s_is_f32;
    __shared__ double s_w[N_LEAVES * 3];
    int t = threadIdx.x;

    if (t == 0) {
        const float* lf = (const float*)leafv;
        int cnt = 0;
        for (int i = 0; i < 64; ++i) {
            float v = fabsf(lf[i]);
            if (isfinite(v) && v > 1e-4f && v < 100.0f) ++cnt;
        }
        s_is_f32 = (cnt >= 52) ? 1 : 0;
    }
    __syncthreads();
    const int f32w = s_is_f32;
    const float*  lf = (const float*) leafv;
    const double* ld = (const double*)leafv;
    const float*  gf = (const float*) gatev;
    const double* gd = (const double*)gatev;

    if (t < N_LEAVES) {
        double a = f32w ? (double)lf[3*t]   : ld[3*t];
        double b = f32w ? (double)lf[3*t+1] : ld[3*t+1];
        double c = f32w ? (double)lf[3*t+2] : ld[3*t+2];
        double m = fmax(a, fmax(b, c));
        double ea = exp(a - m), eb = exp(b - m), ec = exp(c - m);
        double inv = 1.0 / (ea + eb + ec);
        double w[3] = {ea*inv, eb*inv, ec*inv};
        for (int j = 0; j < 3; ++j) {
            s_w[3*t+j] = w[j];
            if (tail_mode == 1) out[tail_off + 3*t + j] = (float)w[j];
        }
    } else if (t < N_LEAVES + 2*N_INTERNAL) {
        int g = t - N_LEAVES;                      // 0..125
        double v0 = f32w ? (double)gf[4*g]   : gd[4*g];
        double v1 = f32w ? (double)gf[4*g+1] : gd[4*g+1];
        double v2 = f32w ? (double)gf[4*g+2] : gd[4*g+2];
        double v3 = f32w ? (double)gf[4*g+3] : gd[4*g+3];
        double m = fmax(fmax(v0, v1), fmax(v2, v3));
        double e0 = exp(v0-m), e1 = exp(v1-m), e2 = exp(v2-m), e3 = exp(v3-m);
        double inv = 1.0 / (e0 + e1 + e2 + e3);
        double p0 = e0*inv, p1 = e1*inv, p2 = e2*inv, p3 = e3*inv;
        if (tail_mode == 1) {
            out[tail_off + 3*N_LEAVES + 4*g]   = (float)p0;
            out[tail_off + 3*N_LEAVES + 4*g+1] = (float)p1;
            out[tail_off + 3*N_LEAVES + 4*g+2] = (float)p2;
            out[tail_off + 3*N_LEAVES + 4*g+3] = (float)p3;
        }
        if (p0 > BYPASS_TH) { p0 = 1.0; p1 = 0.0; p2 = 0.0; p3 = 0.0; }
        if (p1 > BYPASS_TH) { p0 = 0.0; p1 = 1.0; p2 = 0.0; p3 = 0.0; }
        if (p2 > BYPASS_TH) { p0 = 0.0; p1 = 0.0; p2 = 1.0; p3 = 0.0; }
        if (!(p3 > CHILD_EPS)) p3 = 0.0;
        g_g[4*g]   = p0; g_g[4*g+1] = p1; g_g[4*g+2] = p2; g_g[4*g+3] = p3;
        g_gf4[g]   = make_float4((float)p0, (float)p1, (float)p2, (float)p3);
    }
    __syncthreads();

    if (t < N_LEAVES) {
        const double* gp = &g_g[(t >> 1) * 8 + (t & 1) * 4];
        double c0 = gp[0] + gp[3] * s_w[3*t];
        double c1 = gp[1] + gp[3] * s_w[3*t+1];
        double c2 = gp[2] + gp[3] * s_w[3*t+2];
        g_r0f[t] = make_float4((float)c0, (float)c1, (float)c2, 0.0f);
    }
}

// ---------------------------------------------------------------------------
// Round-1 node: children are fp32 (|re| <= ~2e11, im in {0,-pi}). All-fp32
// front-end; only the final 2^(k-1) scale is fp64.
// ---------------------------------------------------------------------------
__device__ __forceinline__ void eval_node_r1(const float4* __restrict__ sf4,
                                             int node,
                                             float clrf, float clif,
                                             float crrf, float crif,
                                             float x0f, float x1f,
                                             double& olr, double& oli) {
    float4 L = sf4[2*node], R = sf4[2*node+1];
    float basel = fmaf(L.y, x0f, fmaf(L.z, x1f, L.x));
    float baser = fmaf(R.y, x0f, fmaf(R.z, x1f, R.x));
    float alr = fmaf(L.w, clrf, basel);
    float ali = L.w * clif;                         // |ali| <= pi
    float brr = fmaf(R.w, crrf, baser);
    float bri = R.w * crif;
    float ac  = fminf(fmaxf(alr, -708.0f), 709.7f);
    float kdf = rintf(ac * 1.44269504f);
    float rf  = fmaf(-kdf, 0.693115234375f, ac);
    rf        = fmaf(-kdf, 3.1946183e-5f, rf);
    float ef2 = exp2f(fmaf(rf, 1.44269504f, 1.0f));   // 2*e^rf
    double sden = __longlong_as_double((long long)((int)kdf - 1 + 1023) << 52);
    float sf, cf;
    __sincosf(ali, &sf, &cf);
    float m2  = fmaxf(fmaf(brr, brr, bri * bri), 1.2e-38f);
    float grf = 0.5f * __log2f(m2) * LN2_F;
    float gif = atan2f(bri, brr);
    olr = clampd(fma((double)(ef2 * cf), sden, -(double)grf));
    oli = clampd(fma((double)(ef2 * sf), sden, -(double)gif));
}

// ---------------------------------------------------------------------------
// Full-range node (rounds 2-5): double blends (p3 from float4, cast);
// single-scale exp; fp32 clog epilogue.
// ---------------------------------------------------------------------------
__device__ __forceinline__ void eval_node_full(const float4* __restrict__ sf4,
                                               int node,
                                               const unsigned long long* __restrict__ ph,
                                               double clr, double cli,
                                               double crr, double cri,
                                               float x0f, float x1f,
                                               double& olr, double& oli) {
    float4 L = sf4[2*node], R = sf4[2*node+1];
    double p3l = (double)L.w, p3r = (double)R.w;
    float basel = fmaf(L.y, x0f, fmaf(L.z, x1f, L.x));
    float baser = fmaf(R.y, x0f, fmaf(R.z, x1f, R.x));
    double alr = fma(p3l, clr, (double)basel);
    double ali = p3l * cli;
    double brr = fma(p3r, crr, (double)baser);
    double bri = p3r * cri;
    // exp(alr): double CW reduction, fp32 core, single fp64 scale.
    double ac = fmin(fmax(alr, -708.0), 709.7);
    double kd = rint(ac * 1.4426950408889634);
    double r  = fma(-kd, 0.6931471805599453, ac);
    r         = fma(-kd, 2.3190468138462996e-17, r);
    float ef2 = exp2f(fmaf((float)r, 1.44269504f, 1.0f));   // 2*e^r
    double sden = __longlong_as_double((long long)((int)kd - 1 + 1023) << 52);
    float sf, cf;
    fast_sincos(ph, ali, sf, cf);
    // clog with 2^k scaling; k in [-998, 1022].
    long long bx = __double_as_longlong(brr) & 0x7fffffffffffffffLL;
    long long by = __double_as_longlong(bri) & 0x7fffffffffffffffLL;
    int ex = (int)(bx >> 52), ey = (int)(by >> 52);
    int em = ex > ey ? ex : ey;
    double sc = __longlong_as_double((long long)(2045 - em) << 52);   // 2^(1022-em)
    float xsf = (float)(brr * sc), ysf = (float)(bri * sc);
    float m2  = fmaxf(fmaf(xsf, xsf, ysf * ysf), 1.2e-38f);
    float grf = fmaf(0.5f, __log2f(m2), (float)(em - 1022)) * LN2_F;
    float gif = atan2f(ysf, xsf);
    olr = clampd(fma((double)(ef2 * cf), sden, -(double)grf));
    oli = clampd(fma((double)(ef2 * sf), sden, -(double)gif));
}

// ---------------------------------------------------------------------------
// Main kernel: 4 lanes per element; lane-local through round 3, shfl after.
// ---------------------------------------------------------------------------
__global__ __launch_bounds__(128)
void tree_kernel(const float* __restrict__ x, float* __restrict__ out,
                 int interleaved) {
    __shared__ float4 sr0[N_LEAVES];
    __shared__ float4 sf4[126];
    __shared__ unsigned long long sph[21];
    int tid = threadIdx.x;
    for (int i = tid; i < N_LEAVES; i += 128) sr0[i] = g_r0f[i];
    for (int i = tid; i < 126; i += 128)      sf4[i] = g_gf4[i];
    if (tid < 21) sph[tid] = PH_TAB[tid];
    __syncthreads();

    int g    = blockIdx.x * 128 + tid;
    int e    = g >> 2;
    int lane = g & 3;

    float x0f = x[2*e];
    float x1f = x[2*e+1];

    // Round 0: fully fp32. |bl| <= ~30 -> er <= ~2e11 fits float.
    float lrf[8], lif[8];
#pragma unroll
    for (int k = 0; k < 8; ++k) {
        int gk = 8*lane + k;
        float4 L = sr0[2*gk], R = sr0[2*gk+1];
        float bl = fmaf(L.y, x0f, fmaf(L.z, x1f, L.x));
        float br = fmaf(R.y, x0f, fmaf(R.z, x1f, R.x));
        float er = __expf(bl);
        float gr = __log2f(fmaxf(fabsf(br), 1e-30f)) * LN2_F;
        lrf[k] = er - gr;
        lif[k] = signbit(br) ? -PI_F : 0.0f;
    }

    // Round 1: fp32 front-end nodes; outputs become double.
    double lr[4], li[4];
#pragma unroll
    for (int j = 0; j < 4; ++j)
        eval_node_r1(sf4, 32 + 4*lane + j,
                     lrf[2*j], lif[2*j], lrf[2*j+1], lif[2*j+1],
                     x0f, x1f, lr[j], li[j]);

    // Round 2.
#pragma unroll
    for (int j = 0; j < 2; ++j)
        eval_node_full(sf4, 48 + 2*lane + j, sph,
                       lr[2*j], li[2*j], lr[2*j+1], li[2*j+1],
                       x0f, x1f, lr[j], li[j]);

    // Round 3.
    eval_node_full(sf4, 56 + lane, sph,
                   lr[0], li[0], lr[1], li[1], x0f, x1f, lr[0], li[0]);

    // Round 4: pair (0,1) on lane 0, (2,3) on lane 2.
    {
        double pr = __shfl_xor_sync(0xffffffffu, lr[0], 1);
        double pi = __shfl_xor_sync(0xffffffffu, li[0], 1);
        eval_node_full(sf4, 60 + (lane >> 1), sph,
                       lr[0], li[0], pr, pi, x0f, x1f, lr[0], li[0]);
    }

    // Round 5: pair on lane 0 (right child from lane 2).
    {
        double pr = __shfl_xor_sync(0xffffffffu, lr[0], 2);
        double pi = __shfl_xor_sync(0xffffffffu, li[0], 2);
        eval_node_full(sf4, 62, sph,
                       lr[0], li[0], pr, pi, x0f, x1f, lr[0], li[0]);
    }

    if (lane == 0) {
        if (interleaved) {
            out[2*e]   = (float)lr[0];
            out[2*e+1] = (float)li[0];
        } else {
            out[e] = (float)lr[0];
        }
    }
}

// ---------------------------------------------------------------------------
extern "C" void kernel_launch(void* const* d_in, const int* in_sizes, int n_in,
                              void* d_out, int out_size) {
    const float* x    = nullptr;
    const void*  leaf = nullptr;
    const void*  gate = nullptr;
    for (int i = 0; i < n_in; ++i) {
        if      (in_sizes[i] == 2 * BATCH)      x    = (const float*)d_in[i];
        else if (in_sizes[i] == 3 * N_LEAVES)   leaf = d_in[i];
        else if (in_sizes[i] == 8 * N_INTERNAL) gate = d_in[i];
    }
    if (!x || !leaf || !gate) return;

    float* out = (float*)d_out;

    const int NPROB = 3*N_LEAVES + 8*N_INTERNAL;  // 696
    int interleaved, tail_mode = 0;
    long long tail_off = 0;

    if (out_size >= 2*BATCH + NPROB) {
        interleaved = 1; tail_mode = 1; tail_off = 2*BATCH;
    } else if (out_size >= 2*BATCH) {
        interleaved = 1;
    } else if (out_size >= BATCH + NPROB) {
        interleaved = 0; tail_mode = 1; tail_off = BATCH;
    } else {
        interleaved = 0;
    }

    prep_kernel<<<1, 192>>>(leaf, gate, out, tail_mode, tail_off);
    tree_kernel<<<(BATCH*4)/128, 128>>>(x, out, interleaved);
}

// round 14
// speedup vs baseline: 1.6687x; 1.0236x over previous
#include <cuda_runtime.h>
#include <math.h>

#define BATCH      262144
#define N_LEAVES   64
#define N_INTERNAL 63

#define CHILD_EPS  2.2204460492503131e-16
#define BYPASS_TH  0.9999999999999998   /* 1 - DBL_EPSILON */
#define CLAMP_V    1e300
#define PI_F       3.14159265358979f
#define LN2_F      0.69314718056f

// Folded parameters (built by prep kernel).
static __device__ double g_g  [N_INTERNAL * 8];  // folded gates (double, for fold step)
static __device__ float4 g_gf4[126];             // per side: (p0,p1,p2,p3) as float
static __device__ float4 g_r0f[N_LEAVES];        // round-0 folded coeffs per leaf

// 2/pi fraction bits (fdlibm two_over_pi), prepended zero word.
static __device__ const unsigned long long PH_TAB[21] = {
    0x0000000000000000ULL,
    0xA2F9836E4E441529ULL, 0xFC2757D1F534DDC0ULL, 0xDB6295993C439041ULL,
    0xFE5163ABDEBBC561ULL, 0xB7246E3A424DD2E0ULL, 0x06492EEA09D1921CULL,
    0xFE1DEB1CB129A73EULL, 0xE88235F52EBB4484ULL, 0xE99C7026B45F7E41ULL,
    0x3991D639835339F4ULL, 0x9C845F8BBDF9283BULL, 0x1FF897FFDE05980FULL,
    0xEF2F118B5A0A6D1FULL, 0x6D367ECF27CB09B7ULL, 0x4F463F669E5FEA2DULL,
    0x7527BAC7EBE5F17BULL, 0x3D0739F78A5292EAULL, 0x6BFB5FB11F8D5D08ULL,
    0x56033046FC7B6BABULL, 0xF0CFBC209AF4361DULL
};

// NaN unreachable post-round-0 -> pure min/max clamp matches nan_to_num+clip.
__device__ __forceinline__ double clampd(double v) {
    return fmin(fmax(v, -CLAMP_V), CLAMP_V);
}

// 2^k as double via high-word construct (single 32-bit shift).
__device__ __forceinline__ double pow2k(int kbiased) {
    return __hiloint2double(kbiased << 20, 0);
}

// Branchy sincos (float outputs): Cody-Waite (<1e6) or 128-bit Payne-Hanek.
__device__ __forceinline__ void fast_sincos(const unsigned long long* __restrict__ ph,
                                            double a, float& sf, float& cf) {
    double aa = fabs(a);
    if (aa < 1.0e6) {
        double kd = rint(a * 0.15915494309189535);
        double r  = fma(-kd, 6.283185307179586, a);
        r         = fma(-kd, 2.4492935982947064e-16, r);
        __sincosf((float)r, &sf, &cf);
    } else {
        int hi = __double2hiint(aa);
        int E  = hi >> 20;                                  // biased exp (aa>0)
        unsigned long long ix = (__double_as_longlong(aa) & 0xFFFFFFFFFFFFFULL) | (1ULL << 52);
        int q = E - 1013;
        int i = q >> 6, sh = q & 63;
        unsigned long long p0 = ph[i], p1 = ph[i+1], p2 = ph[i+2];
        unsigned long long w0 = (p0 << sh) | ((p1 >> 1) >> (63 - sh));
        unsigned long long w1 = (p1 << sh) | ((p2 >> 1) >> (63 - sh));
        // frac(aa * 2/pi) to 2^-75: 128-bit product, keep top word.
        unsigned long long fhi = ix * w0 + __umul64hi(ix, w1);
        double fr  = (double)(long long)fhi * 5.421010862427522e-20;   // [-0.5,0.5)
        double ang = fr * 6.283185307179586;
        __sincosf((float)ang, &sf, &cf);
        sf = (a < 0.0) ? -sf : sf;
    }
}

// ---------------------------------------------------------------------------
// Prep: dtype detect, softmaxes, bypass-fold gates, fold leaves into round-0.
// ---------------------------------------------------------------------------
__global__ void prep_kernel(const void* __restrict__ leafv,
                            const void* __restrict__ gatev,
                            float* __restrict__ out,
                            int tail_mode, long long tail_off) {
    __shared__ int    s_is_f32;
    __shared__ double s_w[N_LEAVES * 3];
    int t = threadIdx.x;

    if (t == 0) {
        const float* lf = (const float*)leafv;
        int cnt = 0;
        for (int i = 0; i < 64; ++i) {
            float v = fabsf(lf[i]);
            if (isfinite(v) && v > 1e-4f && v < 100.0f) ++cnt;
        }
        s_is_f32 = (cnt >= 52) ? 1 : 0;
    }
    __syncthreads();
    const int f32w = s_is_f32;
    const float*  lf = (const float*) leafv;
    const double* ld = (const double*)leafv;
    const float*  gf = (const float*) gatev;
    const double* gd = (const double*)gatev;

    if (t < N_LEAVES) {
        double a = f32w ? (double)lf[3*t]   : ld[3*t];
        double b = f32w ? (double)lf[3*t+1] : ld[3*t+1];
        double c = f32w ? (double)lf[3*t+2] : ld[3*t+2];
        double m = fmax(a, fmax(b, c));
        double ea = exp(a - m), eb = exp(b - m), ec = exp(c - m);
        double inv = 1.0 / (ea + eb + ec);
        double w[3] = {ea*inv, eb*inv, ec*inv};
        for (int j = 0; j < 3; ++j) {
            s_w[3*t+j] = w[j];
            if (tail_mode == 1) out[tail_off + 3*t + j] = (float)w[j];
        }
    } else if (t < N_LEAVES + 2*N_INTERNAL) {
        int g = t - N_LEAVES;                      // 0..125
        double v0 = f32w ? (double)gf[4*g]   : gd[4*g];
        double v1 = f32w ? (double)gf[4*g+1] : gd[4*g+1];
        double v2 = f32w ? (double)gf[4*g+2] : gd[4*g+2];
        double v3 = f32w ? (double)gf[4*g+3] : gd[4*g+3];
        double m = fmax(fmax(v0, v1), fmax(v2, v3));
        double e0 = exp(v0-m), e1 = exp(v1-m), e2 = exp(v2-m), e3 = exp(v3-m);
        double inv = 1.0 / (e0 + e1 + e2 + e3);
        double p0 = e0*inv, p1 = e1*inv, p2 = e2*inv, p3 = e3*inv;
        if (tail_mode == 1) {
            out[tail_off + 3*N_LEAVES + 4*g]   = (float)p0;
            out[tail_off + 3*N_LEAVES + 4*g+1] = (float)p1;
            out[tail_off + 3*N_LEAVES + 4*g+2] = (float)p2;
            out[tail_off + 3*N_LEAVES + 4*g+3] = (float)p3;
        }
        if (p0 > BYPASS_TH) { p0 = 1.0; p1 = 0.0; p2 = 0.0; p3 = 0.0; }
        if (p1 > BYPASS_TH) { p0 = 0.0; p1 = 1.0; p2 = 0.0; p3 = 0.0; }
        if (p2 > BYPASS_TH) { p0 = 0.0; p1 = 0.0; p2 = 1.0; p3 = 0.0; }
        if (!(p3 > CHILD_EPS)) p3 = 0.0;
        g_g[4*g]   = p0; g_g[4*g+1] = p1; g_g[4*g+2] = p2; g_g[4*g+3] = p3;
        g_gf4[g]   = make_float4((float)p0, (float)p1, (float)p2, (float)p3);
    }
    __syncthreads();

    if (t < N_LEAVES) {
        const double* gp = &g_g[(t >> 1) * 8 + (t & 1) * 4];
        double c0 = gp[0] + gp[3] * s_w[3*t];
        double c1 = gp[1] + gp[3] * s_w[3*t+1];
        double c2 = gp[2] + gp[3] * s_w[3*t+2];
        g_r0f[t] = make_float4((float)c0, (float)c1, (float)c2, 0.0f);
    }
}

// ---------------------------------------------------------------------------
// Round-1 node: children fp32 (|re| <= ~2e11, im in {0,-pi}).
// ---------------------------------------------------------------------------
__device__ __forceinline__ void eval_node_r1(const float4* __restrict__ sf4,
                                             int node,
                                             float clrf, float clif,
                                             float crrf, float crif,
                                             float x0f, float x1f,
                                             double& olr, double& oli) {
    float4 L = sf4[2*node], R = sf4[2*node+1];
    float basel = fmaf(L.y, x0f, fmaf(L.z, x1f, L.x));
    float baser = fmaf(R.y, x0f, fmaf(R.z, x1f, R.x));
    float alr = fmaf(L.w, clrf, basel);
    float ali = L.w * clif;                         // |ali| <= pi
    float brr = fmaf(R.w, crrf, baser);
    float bri = R.w * crif;
    float ac  = fminf(fmaxf(alr, -708.0f), 709.7f);
    float kdf = rintf(ac * 1.44269504f);
    float rf  = fmaf(-kdf, 0.693115234375f, ac);
    rf        = fmaf(-kdf, 3.1946183e-5f, rf);
    float ef2 = exp2f(fmaf(rf, 1.44269504f, 1.0f));   // 2*e^rf
    double sden = pow2k((int)kdf + 1022);
    float sf, cf;
    __sincosf(ali, &sf, &cf);
    float m2  = fmaxf(fmaf(brr, brr, bri * bri), 1.2e-38f);
    float grf = 0.5f * __log2f(m2) * LN2_F;
    float gif = atan2f(bri, brr);
    olr = clampd(fma((double)(ef2 * cf), sden, -(double)grf));
    oli = clampd(fma((double)(ef2 * sf), sden, -(double)gif));
}

// ---------------------------------------------------------------------------
// Full-range node (rounds 2-5): double blends; 32-bit exponent surgery.
// ---------------------------------------------------------------------------
__device__ __forceinline__ void eval_node_full(const float4* __restrict__ sf4,
                                               int node,
                                               const unsigned long long* __restrict__ ph,
                                               double clr, double cli,
                                               double crr, double cri,
                                               float x0f, float x1f,
                                               double& olr, double& oli) {
    float4 L = sf4[2*node], R = sf4[2*node+1];
    double p3l = (double)L.w, p3r = (double)R.w;
    float basel = fmaf(L.y, x0f, fmaf(L.z, x1f, L.x));
    float baser = fmaf(R.y, x0f, fmaf(R.z, x1f, R.x));
    double alr = fma(p3l, clr, (double)basel);
    double ali = p3l * cli;
    double brr = fma(p3r, crr, (double)baser);
    double bri = p3r * cri;
    // exp(alr): double CW reduction, fp32 core, single fp64 scale.
    double ac = fmin(fmax(alr, -708.0), 709.7);
    double kd = rint(ac * 1.4426950408889634);
    double r  = fma(-kd, 0.6931471805599453, ac);
    r         = fma(-kd, 2.3190468138462996e-17, r);
    float ef2 = exp2f(fmaf((float)r, 1.44269504f, 1.0f));   // 2*e^r
    double sden = pow2k((int)kd + 1022);
    float sf, cf;
    fast_sincos(ph, ali, sf, cf);
    // clog with 2^k scaling; exponents via high words only.
    int ex = (__double2hiint(brr) >> 20) & 0x7ff;
    int ey = (__double2hiint(bri) >> 20) & 0x7ff;
    int em = ex > ey ? ex : ey;
    double sc = pow2k(2045 - em);                           // 2^(1022-em)
    float xsf = (float)(brr * sc), ysf = (float)(bri * sc);
    float m2  = fmaxf(fmaf(xsf, xsf, ysf * ysf), 1.2e-38f);
    float grf = fmaf(0.5f, __log2f(m2), (float)(em - 1022)) * LN2_F;
    float gif = atan2f(ysf, xsf);
    olr = clampd(fma((double)(ef2 * cf), sden, -(double)grf));
    oli = clampd(fma((double)(ef2 * sf), sden, -(double)gif));
}

// ---------------------------------------------------------------------------
// Main kernel: 4 lanes per element; lane-local through round 3, shfl after.
// ---------------------------------------------------------------------------
__global__ __launch_bounds__(128)
void tree_kernel(const float* __restrict__ x, float* __restrict__ out,
                 int interleaved) {
    __shared__ float4 sr0[N_LEAVES];
    __shared__ float4 sf4[126];
    __shared__ unsigned long long sph[21];
    int tid = threadIdx.x;
    for (int i = tid; i < N_LEAVES; i += 128) sr0[i] = g_r0f[i];
    for (int i = tid; i < 126; i += 128)      sf4[i] = g_gf4[i];
    if (tid < 21) sph[tid] = PH_TAB[tid];
    __syncthreads();

    int g    = blockIdx.x * 128 + tid;
    int e    = g >> 2;
    int lane = g & 3;

    float x0f = x[2*e];
    float x1f = x[2*e+1];

    // Round 0: fully fp32.
    float lrf[8], lif[8];
#pragma unroll
    for (int k = 0; k < 8; ++k) {
        int gk = 8*lane + k;
        float4 L = sr0[2*gk], R = sr0[2*gk+1];
        float bl = fmaf(L.y, x0f, fmaf(L.z, x1f, L.x));
        float br = fmaf(R.y, x0f, fmaf(R.z, x1f, R.x));
        float er = __expf(bl);
        float gr = __log2f(fmaxf(fabsf(br), 1e-30f)) * LN2_F;
        lrf[k] = er - gr;
        lif[k] = signbit(br) ? -PI_F : 0.0f;
    }

    // Round 1: fp32 front-end nodes; outputs become double.
    double lr[4], li[4];
#pragma unroll
    for (int j = 0; j < 4; ++j)
        eval_node_r1(sf4, 32 + 4*lane + j,
                     lrf[2*j], lif[2*j], lrf[2*j+1], lif[2*j+1],
                     x0f, x1f, lr[j], li[j]);

    // Round 2.
#pragma unroll
    for (int j = 0; j < 2; ++j)
        eval_node_full(sf4, 48 + 2*lane + j, sph,
                       lr[2*j], li[2*j], lr[2*j+1], li[2*j+1],
                       x0f, x1f, lr[j], li[j]);

    // Round 3.
    eval_node_full(sf4, 56 + lane, sph,
                   lr[0], li[0], lr[1], li[1], x0f, x1f, lr[0], li[0]);

    // Round 4: pair (0,1) on lane 0, (2,3) on lane 2.
    {
        double pr = __shfl_xor_sync(0xffffffffu, lr[0], 1);
        double pi = __shfl_xor_sync(0xffffffffu, li[0], 1);
        eval_node_full(sf4, 60 + (lane >> 1), sph,
                       lr[0], li[0], pr, pi, x0f, x1f, lr[0], li[0]);
    }

    // Round 5: pair on lane 0 (right child from lane 2).
    {
        double pr = __shfl_xor_sync(0xffffffffu, lr[0], 2);
        double pi = __shfl_xor_sync(0xffffffffu, li[0], 2);
        eval_node_full(sf4, 62, sph,
                       lr[0], li[0], pr, pi, x0f, x1f, lr[0], li[0]);
    }

    if (lane == 0) {
        if (interleaved) {
            out[2*e]   = (float)lr[0];
            out[2*e+1] = (float)li[0];
        } else {
            out[e] = (float)lr[0];
        }
    }
}

// ---------------------------------------------------------------------------
extern "C" void kernel_launch(void* const* d_in, const int* in_sizes, int n_in,
                              void* d_out, int out_size) {
    const float* x    = nullptr;
    const void*  leaf = nullptr;
    const void*  gate = nullptr;
    for (int i = 0; i < n_in; ++i) {
        if      (in_sizes[i] == 2 * BATCH)      x    = (const float*)d_in[i];
        else if (in_sizes[i] == 3 * N_LEAVES)   leaf = d_in[i];
        else if (in_sizes[i] == 8 * N_INTERNAL) gate = d_in[i];
    }
    if (!x || !leaf || !gate) return;

    float* out = (float*)d_out;

    const int NPROB = 3*N_LEAVES + 8*N_INTERNAL;  // 696
    int interleaved, tail_mode = 0;
    long long tail_off = 0;

    if (out_size >= 2*BATCH + NPROB) {
        interleaved = 1; tail_mode = 1; tail_off = 2*BATCH;
    } else if (out_size >= 2*BATCH) {
        interleaved = 1;
    } else if (out_size >= BATCH + NPROB) {
        interleaved = 0; tail_mode = 1; tail_off = BATCH;
    } else {
        interleaved = 0;
    }

    prep_kernel<<<1, 192>>>(leaf, gate, out, tail_mode, tail_off);
    tree_kernel<<<(BATCH*4)/128, 128>>>(x, out, interleaved);
}

// round 15
// speedup vs baseline: 1.9011x; 1.1393x over previous
#include <cuda_runtime.h>
#include <math.h>

#define BATCH      262144
#define N_LEAVES   64
#define N_INTERNAL 63

#define CHILD_EPS  2.2204460492503131e-16
#define BYPASS_TH  0.9999999999999998   /* 1 - DBL_EPSILON */
#define CLAMP_V    1e300
#define PI_F       3.14159265358979f
#define LN2_F      0.69314718056f

// Folded parameters (built by prep kernel).
static __device__ double g_g  [N_INTERNAL * 8];  // folded gates (double, for fold step)
static __device__ float4 g_gf4[126];             // per side: (p0,p1,p2,p3) as float
static __device__ float4 g_r0f[N_LEAVES];        // round-0 folded coeffs per leaf

// 2/pi fraction bits (fdlibm two_over_pi), prepended zero word.
static __device__ const unsigned long long PH_TAB[21] = {
    0x0000000000000000ULL,
    0xA2F9836E4E441529ULL, 0xFC2757D1F534DDC0ULL, 0xDB6295993C439041ULL,
    0xFE5163ABDEBBC561ULL, 0xB7246E3A424DD2E0ULL, 0x06492EEA09D1921CULL,
    0xFE1DEB1CB129A73EULL, 0xE88235F52EBB4484ULL, 0xE99C7026B45F7E41ULL,
    0x3991D639835339F4ULL, 0x9C845F8BBDF9283BULL, 0x1FF897FFDE05980FULL,
    0xEF2F118B5A0A6D1FULL, 0x6D367ECF27CB09B7ULL, 0x4F463F669E5FEA2DULL,
    0x7527BAC7EBE5F17BULL, 0x3D0739F78A5292EAULL, 0x6BFB5FB11F8D5D08ULL,
    0x56033046FC7B6BABULL, 0xF0CFBC209AF4361DULL
};

// NaN unreachable post-round-0 -> pure min/max clamp matches nan_to_num+clip.
__device__ __forceinline__ double clampd(double v) {
    return fmin(fmax(v, -CLAMP_V), CLAMP_V);
}

// 2^k as double via high-word construct (single 32-bit shift).
__device__ __forceinline__ double pow2k(int kbiased) {
    return __hiloint2double(kbiased << 20, 0);
}

// Branchy sincos (float outputs): Cody-Waite (<1e6) or 128-bit Payne-Hanek.
__device__ __forceinline__ void fast_sincos(const unsigned long long* __restrict__ ph,
                                            double a, float& sf, float& cf) {
    double aa = fabs(a);
    if (aa < 1.0e6) {
        double kd = rint(a * 0.15915494309189535);
        double r  = fma(-kd, 6.283185307179586, a);
        r         = fma(-kd, 2.4492935982947064e-16, r);
        __sincosf((float)r, &sf, &cf);
    } else {
        int hi = __double2hiint(aa);
        int E  = hi >> 20;                                  // biased exp (aa>0)
        unsigned long long ix = (__double_as_longlong(aa) & 0xFFFFFFFFFFFFFULL) | (1ULL << 52);
        int q = E - 1013;
        int i = q >> 6, sh = q & 63;
        unsigned long long p0 = ph[i], p1 = ph[i+1], p2 = ph[i+2];
        unsigned long long w0 = (p0 << sh) | ((p1 >> 1) >> (63 - sh));
        unsigned long long w1 = (p1 << sh) | ((p2 >> 1) >> (63 - sh));
        unsigned long long fhi = ix * w0 + __umul64hi(ix, w1);
        double fr  = (double)(long long)fhi * 5.421010862427522e-20;   // [-0.5,0.5)
        double ang = fr * 6.283185307179586;
        __sincosf((float)ang, &sf, &cf);
        sf = (a < 0.0) ? -sf : sf;
    }
}

// ---------------------------------------------------------------------------
// Prep: dtype detect, softmaxes, bypass-fold gates, fold leaves into round-0.
// ---------------------------------------------------------------------------
__global__ void prep_kernel(const void* __restrict__ leafv,
                            const void* __restrict__ gatev,
                            float* __restrict__ out,
                            int tail_mode, long long tail_off) {
    __shared__ int    s_is_f32;
    __shared__ double s_w[N_LEAVES * 3];
    int t = threadIdx.x;

    if (t == 0) {
        const float* lf = (const float*)leafv;
        int cnt = 0;
        for (int i = 0; i < 64; ++i) {
            float v = fabsf(lf[i]);
            if (isfinite(v) && v > 1e-4f && v < 100.0f) ++cnt;
        }
        s_is_f32 = (cnt >= 52) ? 1 : 0;
    }
    __syncthreads();
    const int f32w = s_is_f32;
    const float*  lf = (const float*) leafv;
    const double* ld = (const double*)leafv;
    const float*  gf = (const float*) gatev;
    const double* gd = (const double*)gatev;

    if (t < N_LEAVES) {
        double a = f32w ? (double)lf[3*t]   : ld[3*t];
        double b = f32w ? (double)lf[3*t+1] : ld[3*t+1];
        double c = f32w ? (double)lf[3*t+2] : ld[3*t+2];
        double m = fmax(a, fmax(b, c));
        double ea = exp(a - m), eb = exp(b - m), ec = exp(c - m);
        double inv = 1.0 / (ea + eb + ec);
        double w[3] = {ea*inv, eb*inv, ec*inv};
        for (int j = 0; j < 3; ++j) {
            s_w[3*t+j] = w[j];
            if (tail_mode == 1) out[tail_off + 3*t + j] = (float)w[j];
        }
    } else if (t < N_LEAVES + 2*N_INTERNAL) {
        int g = t - N_LEAVES;                      // 0..125
        double v0 = f32w ? (double)gf[4*g]   : gd[4*g];
        double v1 = f32w ? (double)gf[4*g+1] : gd[4*g+1];
        double v2 = f32w ? (double)gf[4*g+2] : gd[4*g+2];
        double v3 = f32w ? (double)gf[4*g+3] : gd[4*g+3];
        double m = fmax(fmax(v0, v1), fmax(v2, v3));
        double e0 = exp(v0-m), e1 = exp(v1-m), e2 = exp(v2-m), e3 = exp(v3-m);
        double inv = 1.0 / (e0 + e1 + e2 + e3);
        double p0 = e0*inv, p1 = e1*inv, p2 = e2*inv, p3 = e3*inv;
        if (tail_mode == 1) {
            out[tail_off + 3*N_LEAVES + 4*g]   = (float)p0;
            out[tail_off + 3*N_LEAVES + 4*g+1] = (float)p1;
            out[tail_off + 3*N_LEAVES + 4*g+2] = (float)p2;
            out[tail_off + 3*N_LEAVES + 4*g+3] = (float)p3;
        }
        if (p0 > BYPASS_TH) { p0 = 1.0; p1 = 0.0; p2 = 0.0; p3 = 0.0; }
        if (p1 > BYPASS_TH) { p0 = 0.0; p1 = 1.0; p2 = 0.0; p3 = 0.0; }
        if (p2 > BYPASS_TH) { p0 = 0.0; p1 = 0.0; p2 = 1.0; p3 = 0.0; }
        if (!(p3 > CHILD_EPS)) p3 = 0.0;
        g_g[4*g]   = p0; g_g[4*g+1] = p1; g_g[4*g+2] = p2; g_g[4*g+3] = p3;
        g_gf4[g]   = make_float4((float)p0, (float)p1, (float)p2, (float)p3);
    }
    __syncthreads();

    if (t < N_LEAVES) {
        const double* gp = &g_g[(t >> 1) * 8 + (t & 1) * 4];
        double c0 = gp[0] + gp[3] * s_w[3*t];
        double c1 = gp[1] + gp[3] * s_w[3*t+1];
        double c2 = gp[2] + gp[3] * s_w[3*t+2];
        g_r0f[t] = make_float4((float)c0, (float)c1, (float)c2, 0.0f);
    }
}

// ---------------------------------------------------------------------------
// Round-1 node: children fp32 (|re| <= ~2e11, im in {0,-pi}).
// ---------------------------------------------------------------------------
__device__ __forceinline__ void eval_node_r1(const float4* __restrict__ sf4,
                                             int node,
                                             float clrf, float clif,
                                             float crrf, float crif,
                                             float x0f, float x1f,
                                             double& olr, double& oli) {
    float4 L = sf4[2*node], R = sf4[2*node+1];
    float basel = fmaf(L.y, x0f, fmaf(L.z, x1f, L.x));
    float baser = fmaf(R.y, x0f, fmaf(R.z, x1f, R.x));
    float alr = fmaf(L.w, clrf, basel);
    float ali = L.w * clif;                         // |ali| <= pi
    float brr = fmaf(R.w, crrf, baser);
    float bri = R.w * crif;
    float ac  = fminf(fmaxf(alr, -708.0f), 709.7f);
    float kdf = rintf(ac * 1.44269504f);
    float rf  = fmaf(-kdf, 0.693115234375f, ac);
    rf        = fmaf(-kdf, 3.1946183e-5f, rf);
    float ef2 = exp2f(fmaf(rf, 1.44269504f, 1.0f));   // 2*e^rf
    double sden = pow2k((int)kdf + 1022);
    float sf, cf;
    __sincosf(ali, &sf, &cf);
    float m2  = fmaxf(fmaf(brr, brr, bri * bri), 1.2e-38f);
    float grf = 0.5f * __log2f(m2) * LN2_F;
    float gif = atan2f(bri, brr);
    olr = clampd(fma((double)(ef2 * cf), sden, -(double)grf));
    oli = clampd(fma((double)(ef2 * sf), sden, -(double)gif));
}

// ---------------------------------------------------------------------------
// Full-range node (rounds 2-5): double blends; 32-bit exponent surgery.
// ---------------------------------------------------------------------------
__device__ __forceinline__ void eval_node_full(const float4* __restrict__ sf4,
                                               int node,
                                               const unsigned long long* __restrict__ ph,
                                               double clr, double cli,
                                               double crr, double cri,
                                               float x0f, float x1f,
                                               double& olr, double& oli) {
    float4 L = sf4[2*node], R = sf4[2*node+1];
    double p3l = (double)L.w, p3r = (double)R.w;
    float basel = fmaf(L.y, x0f, fmaf(L.z, x1f, L.x));
    float baser = fmaf(R.y, x0f, fmaf(R.z, x1f, R.x));
    double alr = fma(p3l, clr, (double)basel);
    double ali = p3l * cli;
    double brr = fma(p3r, crr, (double)baser);
    double bri = p3r * cri;
    // exp(alr): double CW reduction, fp32 core, single fp64 scale.
    double ac = fmin(fmax(alr, -708.0), 709.7);
    double kd = rint(ac * 1.4426950408889634);
    double r  = fma(-kd, 0.6931471805599453, ac);
    r         = fma(-kd, 2.3190468138462996e-17, r);
    float ef2 = exp2f(fmaf((float)r, 1.44269504f, 1.0f));   // 2*e^r
    double sden = pow2k((int)kd + 1022);
    float sf, cf;
    fast_sincos(ph, ali, sf, cf);
    // clog with 2^k scaling; exponents via high words only.
    int ex = (__double2hiint(brr) >> 20) & 0x7ff;
    int ey = (__double2hiint(bri) >> 20) & 0x7ff;
    int em = ex > ey ? ex : ey;
    double sc = pow2k(2045 - em);                           // 2^(1022-em)
    float xsf = (float)(brr * sc), ysf = (float)(bri * sc);
    float m2  = fmaxf(fmaf(xsf, xsf, ysf * ysf), 1.2e-38f);
    float grf = fmaf(0.5f, __log2f(m2), (float)(em - 1022)) * LN2_F;
    float gif = atan2f(ysf, xsf);
    olr = clampd(fma((double)(ef2 * cf), sden, -(double)grf));
    oli = clampd(fma((double)(ef2 * sf), sden, -(double)gif));
}

// ---------------------------------------------------------------------------
// Main kernel: 2 lanes per element. Lane owns 16 round-0 pairs; everything is
// lane-local through round 4; only round 5 needs one shfl_xor(1).
// ---------------------------------------------------------------------------
__global__ __launch_bounds__(128)
void tree_kernel(const float* __restrict__ x, float* __restrict__ out,
                 int interleaved) {
    __shared__ float4 sr0[N_LEAVES];
    __shared__ float4 sf4[126];
    __shared__ unsigned long long sph[21];
    int tid = threadIdx.x;
    for (int i = tid; i < N_LEAVES; i += 128) sr0[i] = g_r0f[i];
    for (int i = tid; i < 126; i += 128)      sf4[i] = g_gf4[i];
    if (tid < 21) sph[tid] = PH_TAB[tid];
    __syncthreads();

    int g    = blockIdx.x * 128 + tid;
    int e    = g >> 1;
    int lane = g & 1;

    float x0f = x[2*e];
    float x1f = x[2*e+1];

    // Round 0: 16 real pairs for this lane, fully fp32.
    float lrf[16], lif[16];
#pragma unroll
    for (int k = 0; k < 16; ++k) {
        int gk = 16*lane + k;
        float4 L = sr0[2*gk], R = sr0[2*gk+1];
        float bl = fmaf(L.y, x0f, fmaf(L.z, x1f, L.x));
        float br = fmaf(R.y, x0f, fmaf(R.z, x1f, R.x));
        float er = __expf(bl);
        float gr = __log2f(fmaxf(fabsf(br), 1e-30f)) * LN2_F;
        lrf[k] = er - gr;
        lif[k] = signbit(br) ? -PI_F : 0.0f;
    }

    // Round 1: 8 fp32 front-end nodes; outputs become double.
    double lr[8], li[8];
#pragma unroll
    for (int j = 0; j < 8; ++j)
        eval_node_r1(sf4, 32 + 8*lane + j,
                     lrf[2*j], lif[2*j], lrf[2*j+1], lif[2*j+1],
                     x0f, x1f, lr[j], li[j]);

    // Round 2: 4 nodes.
#pragma unroll
    for (int j = 0; j < 4; ++j)
        eval_node_full(sf4, 48 + 4*lane + j, sph,
                       lr[2*j], li[2*j], lr[2*j+1], li[2*j+1],
                       x0f, x1f, lr[j], li[j]);

    // Round 3: 2 nodes.
#pragma unroll
    for (int j = 0; j < 2; ++j)
        eval_node_full(sf4, 56 + 2*lane + j, sph,
                       lr[2*j], li[2*j], lr[2*j+1], li[2*j+1],
                       x0f, x1f, lr[j], li[j]);

    // Round 4: 1 node, still lane-local.
    eval_node_full(sf4, 60 + lane, sph,
                   lr[0], li[0], lr[1], li[1], x0f, x1f, lr[0], li[0]);

    // Round 5: node 62; right child comes from lane 1 via shfl.
    {
        double pr = __shfl_xor_sync(0xffffffffu, lr[0], 1);
        double pi = __shfl_xor_sync(0xffffffffu, li[0], 1);
        eval_node_full(sf4, 62, sph,
                       lr[0], li[0], pr, pi, x0f, x1f, lr[0], li[0]);
    }

    if (lane == 0) {
        if (interleaved) {
            out[2*e]   = (float)lr[0];
            out[2*e+1] = (float)li[0];
        } else {
            out[e] = (float)lr[0];
        }
    }
}

// ---------------------------------------------------------------------------
extern "C" void kernel_launch(void* const* d_in, const int* in_sizes, int n_in,
                              void* d_out, int out_size) {
    const float* x    = nullptr;
    const void*  leaf = nullptr;
    const void*  gate = nullptr;
    for (int i = 0; i < n_in; ++i) {
        if      (in_sizes[i] == 2 * BATCH)      x    = (const float*)d_in[i];
        else if (in_sizes[i] == 3 * N_LEAVES)   leaf = d_in[i];
        else if (in_sizes[i] == 8 * N_INTERNAL) gate = d_in[i];
    }
    if (!x || !leaf || !gate) return;

    float* out = (float*)d_out;

    const int NPROB = 3*N_LEAVES + 8*N_INTERNAL;  // 696
    int interleaved, tail_mode = 0;
    long long tail_off = 0;

    if (out_size >= 2*BATCH + NPROB) {
        interleaved = 1; tail_mode = 1; tail_off = 2*BATCH;
    } else if (out_size >= 2*BATCH) {
        interleaved = 1;
    } else if (out_size >= BATCH + NPROB) {
        interleaved = 0; tail_mode = 1; tail_off = BATCH;
    } else {
        interleaved = 0;
    }

    prep_kernel<<<1, 192>>>(leaf, gate, out, tail_mode, tail_off);
    tree_kernel<<<(BATCH*2)/128, 128>>>(x, out, interleaved);
}